// round 10
// baseline (speedup 1.0000x reference)
#include <cuda_runtime.h>
#include <cstdint>
#include <cstddef>

typedef unsigned long long ull;

#define Tlen   512
#define NB     4096
#define NTHR   512          // 16 warps: 4 per layer
#define NTICKS (Tlen + 4)   // layer l does t=T-l; fc does t=T-4
#define CLU    2            // cluster size; each cluster handles 64 batches

// ---- shared memory layout (float offsets), all 16B-aligned ----
#define W0_OFF    0                    // 100 rows x 28  = 2800  : L1 fused [Wih1|Whh1|pad2]
#define W123_OFF  2800                 // 3 x 100 x 52   = 15600 : L2-4 fused [Wih|0|Whh|0]
#define BIAS_OFF  (W123_OFF + 15600)   // 18400 : [4 layer][25 unit][4 gate] fused bih+bhh
#define WFC_OFF   (BIAS_OFF + 400)     // 18800 : 52-float fc row (W_fc at [26..50])
#define V0_OFF    (WFC_OFF + 52)       // 18852 : [2 set][2 buf][32 lane][28]
#define V0_SET    1792
#define V123_OFF  (V0_OFF + 2 * V0_SET)   // 22436 : [2 set][3 layer][2 buf][32][52]
#define V123_SET  9984
#define SMEM_FLOATS (V123_OFF + 2 * V123_SET)  // 42404 floats = 169616 bytes

__device__ __forceinline__ ull pack2(float lo, float hi) {
    return (ull)__float_as_uint(lo) | ((ull)__float_as_uint(hi) << 32);
}
__device__ __forceinline__ float hsum2(ull v) {
    float lo = __uint_as_float((unsigned)v);
    float hi = __uint_as_float((unsigned)(v >> 32));
    return lo + hi;
}
__device__ __forceinline__ void fma2(ull& acc, ull a, ull b) {
    asm("fma.rn.f32x2 %0, %1, %2, %0;" : "+l"(acc) : "l"(a), "l"(b));
}
__device__ __forceinline__ float fast_sig(float x) {
    float e, r;
    asm("ex2.approx.ftz.f32 %0, %1;" : "=f"(e) : "f"(x * -1.4426950408889634f));
    asm("rcp.approx.ftz.f32 %0, %1;" : "=f"(r) : "f"(e + 1.0f));
    return r;
}
__device__ __forceinline__ float fast_tanh(float x) {
    return fmaf(2.0f, fast_sig(2.0f * x), -1.0f);
}
__device__ __forceinline__ uint32_t smem_u32(const void* p) {
    uint32_t a;
    asm("{ .reg .u64 t; cvta.to.shared.u64 t, %1; cvt.u32.u64 %0, t; }" : "=r"(a) : "l"(p));
    return a;
}
__device__ __forceinline__ uint32_t my_ctarank() {
    uint32_t r; asm("mov.u32 %0, %%cluster_ctarank;" : "=r"(r)); return r;
}
__device__ __forceinline__ uint32_t mapa_u32(uint32_t addr, uint32_t rank) {
    uint32_t r;
    asm("mapa.shared::cluster.u32 %0, %1, %2;" : "=r"(r) : "r"(addr), "r"(rank));
    return r;
}
__device__ __forceinline__ void st_cluster_f32(uint32_t addr, float v) {
    asm volatile("st.shared::cluster.f32 [%0], %1;" :: "r"(addr), "f"(v) : "memory");
}
__device__ __forceinline__ void cluster_arrive() {
    asm volatile("barrier.cluster.arrive.aligned;" ::: "memory");
}
__device__ __forceinline__ void cluster_wait() {
    asm volatile("barrier.cluster.wait.aligned;" ::: "memory");
}

// 4-gate dot products for one unit, v-row already in registers.
template<int NCH>
__device__ __forceinline__ void gates4reg(const ulonglong2* __restrict__ V,
    const float* __restrict__ w0, const float* __restrict__ w1,
    const float* __restrict__ w2, const float* __restrict__ w3,
    float b0, float b1, float b2, float b3,
    float& s0, float& s1, float& s2, float& s3)
{
    ull A0 = pack2(b0, 0.f), B0 = 0ull;
    ull A1 = pack2(b1, 0.f), B1 = 0ull;
    ull A2 = pack2(b2, 0.f), B2 = 0ull;
    ull A3 = pack2(b3, 0.f), B3 = 0ull;
    const ulonglong2* W0 = (const ulonglong2*)w0;
    const ulonglong2* W1 = (const ulonglong2*)w1;
    const ulonglong2* W2 = (const ulonglong2*)w2;
    const ulonglong2* W3 = (const ulonglong2*)w3;
#pragma unroll
    for (int ch = 0; ch < NCH; ++ch) {
        ulonglong2 w;
        w = W0[ch]; fma2(A0, w.x, V[ch].x); fma2(B0, w.y, V[ch].y);
        w = W1[ch]; fma2(A1, w.x, V[ch].x); fma2(B1, w.y, V[ch].y);
        w = W2[ch]; fma2(A2, w.x, V[ch].x); fma2(B2, w.y, V[ch].y);
        w = W3[ch]; fma2(A3, w.x, V[ch].x); fma2(B3, w.y, V[ch].y);
    }
    s0 = hsum2(A0) + hsum2(B0);
    s1 = hsum2(A1) + hsum2(B1);
    s2 = hsum2(A2) + hsum2(B2);
    s3 = hsum2(A3) + hsum2(B3);
}

__global__ void __launch_bounds__(NTHR) __cluster_dims__(CLU, 1, 1) lstm_kernel(
    const float* __restrict__ x,
    const float* __restrict__ Wih1, const float* __restrict__ Whh1,
    const float* __restrict__ bih1, const float* __restrict__ bhh1,
    const float* __restrict__ Wih2, const float* __restrict__ Whh2,
    const float* __restrict__ bih2, const float* __restrict__ bhh2,
    const float* __restrict__ Wih3, const float* __restrict__ Whh3,
    const float* __restrict__ bih3, const float* __restrict__ bhh3,
    const float* __restrict__ Wih4, const float* __restrict__ Whh4,
    const float* __restrict__ bih4, const float* __restrict__ bhh4,
    const float* __restrict__ Wfc, const float* __restrict__ bfc,
    float* __restrict__ out, int write_states)
{
    extern __shared__ float smem[];
    const int tid = threadIdx.x;

    // ---- stage fused weights (full copy in each block; reads filtered by ownership) ----
    for (int i = tid; i < 2800; i += NTHR) {
        int g = i / 28, p = i - g * 28;
        float v = 0.f;
        if (p == 0)      v = Wih1[g];
        else if (p < 26) v = Whh1[g * 25 + p - 1];
        smem[W0_OFF + i] = v;
    }
    {
        const float* WihL[3] = {Wih2, Wih3, Wih4};
        const float* WhhL[3] = {Whh2, Whh3, Whh4};
        for (int i = tid; i < 15600; i += NTHR) {
            int l = i / 5200; int r = i - l * 5200;
            int g = r / 52,   p = r - g * 52;
            float v = 0.f;
            if (p < 25)                 v = WihL[l][g * 25 + p];
            else if (p >= 26 && p < 51) v = WhhL[l][g * 25 + p - 26];
            smem[W123_OFF + i] = v;
        }
        const float* bi[4] = {bih1, bih2, bih3, bih4};
        const float* bh[4] = {bhh1, bhh2, bhh3, bhh4};
        for (int i = tid; i < 400; i += NTHR) {
            int l = i / 100, r = i - l * 100, u = r >> 2, j = r & 3;
            smem[BIAS_OFF + i] = bi[l][j * 25 + u] + bh[l][j * 25 + u];
        }
    }
    for (int i = tid; i < 52; i += NTHR)
        smem[WFC_OFF + i] = (i >= 26 && i < 51) ? Wfc[i - 26] : 0.f;
    for (int i = tid; i < 2 * V0_SET + 2 * V123_SET; i += NTHR) smem[V0_OFF + i] = 0.f;

    const int lane  = tid & 31;
    const int wid   = tid >> 5;
    const int layer = wid >> 2;                       // 0..3
    const int wl    = wid & 3;                        // warp-in-layer
    const uint32_t rank = my_ctarank();               // 0 or 1
    // unit ownership: rank0 -> 0..12 (13 units, split 3,3,3,4); rank1 -> 13..24 (3,3,3,3)
    const int ubase = rank ? 13 : 0;
    const int uown  = rank ? 12 : 13;
    const int first = ubase + (wl * uown) / 4;
    const int nu    = ubase + ((wl + 1) * uown) / 4 - first;

    const int cb   = (blockIdx.x >> 1) * 64;          // cluster batch base
    const int gbS[2] = { cb + lane, cb + 32 + lane }; // global batch per set

    const uint32_t base_u32 = smem_u32(smem);
    const uint32_t peer_u32 = mapa_u32(base_u32, rank ^ 1);

    float xreg[2] = {0.f, 0.f};
    float bfc_reg = 0.f;
    if (wid == 0) {
        smem[V0_OFF + 0 * V0_SET + lane * 28 + 0] = x[gbS[0]];     // x(0)
        smem[V0_OFF + 1 * V0_SET + lane * 28 + 0] = x[gbS[1]];
        xreg[0] = x[(size_t)NB + gbS[0]];                          // prefetch x(1)
        xreg[1] = x[(size_t)NB + gbS[1]];
    }
    if (rank == 0 && wid == 1) bfc_reg = bfc[0];
    __syncthreads();
    cluster_arrive(); cluster_wait();    // both blocks init'd before any remote write

    float c[8];                           // c[set*4 + k]
#pragma unroll
    for (int i = 0; i < 8; ++i) c[i] = 0.f;

    // per-set row bases (float index into smem), this lane's row
    int rowIdx[2];                        // v-row base for this warp's layer
    int childIdx[2];                      // next layer's row base (input slots)
#pragma unroll
    for (int s = 0; s < 2; ++s) {
        rowIdx[s] = (layer == 0)
            ? V0_OFF + s * V0_SET + lane * 28
            : V123_OFF + s * V123_SET + (layer - 1) * 3328 + lane * 52;
        childIdx[s] = (layer < 3)
            ? V123_OFF + s * V123_SET + layer * 3328 + lane * 52
            : 0;
    }
    const float* biasS = smem + BIAS_OFF + layer * 100;
    const float* wfc   = smem + WFC_OFF;

    for (int T = 0; T < NTICKS; ++T) {
        const int par = (T + layer) & 1;

        // ---- x stager (warp 0 of each block): stage x(T+1), prefetch x(T+2) ----
        if (wid == 0) {
            int nb = (T + 1) & 1;
            smem[V0_OFF + 0 * V0_SET + nb * 896 + lane * 28] = xreg[0];
            smem[V0_OFF + 1 * V0_SET + nb * 896 + lane * 28] = xreg[1];
            int t2 = (T + 2 < Tlen) ? T + 2 : Tlen - 1;
            xreg[0] = x[(size_t)t2 * NB + gbS[0]];
            xreg[1] = x[(size_t)t2 * NB + gbS[1]];
        }
        // ---- fc (rank 0, warp 1): y(T-4) from h4(T-4) in v3 buffer (T+1)&1 ----
        if (rank == 0 && wid == 1 && T >= 4) {
#pragma unroll
            for (int s = 0; s < 2; ++s) {
                const float* v3 = smem + V123_OFF + s * V123_SET + 2 * 3328
                                + lane * 52 + ((T + 1) & 1) * 1664;
                const ulonglong2* V3 = (const ulonglong2*)v3;
                const ulonglong2* WF = (const ulonglong2*)wfc;
                ull A = pack2(bfc_reg, 0.f), B = 0ull;
#pragma unroll
                for (int ch = 6; ch < 13; ++ch) {
                    ulonglong2 hv = V3[ch]; ulonglong2 w = WF[ch];
                    fma2(A, w.x, hv.x); fma2(B, w.y, hv.y);
                }
                out[(size_t)(T - 4) * NB + gbS[s]] = hsum2(A) + hsum2(B);
            }
        }

        const bool act = (T >= layer) && (T - layer < Tlen);
        if (act) {
#pragma unroll
            for (int s = 0; s < 2; ++s) {
                if (layer == 0) {
                    ulonglong2 V[7];
                    const ulonglong2* src = (const ulonglong2*)(smem + rowIdx[s] + par * 896);
#pragma unroll
                    for (int ch = 0; ch < 7; ++ch) V[ch] = src[ch];
#pragma unroll
                    for (int k = 0; k < 4; ++k) if (k < nu) {
                        const int u = first + k;
                        const float* wr = smem + W0_OFF + u * 28;
                        float4 bb = *(const float4*)(biasS + u * 4);
                        float s0, s1, s2, s3;
                        gates4reg<7>(V, wr, wr + 700, wr + 1400, wr + 2100,
                                     bb.x, bb.y, bb.z, bb.w, s0, s1, s2, s3);
                        float fi = fast_sig(s0), ff = fast_sig(s1);
                        float fg = fast_tanh(s2), fo = fast_sig(s3);
                        c[s * 4 + k] = fmaf(ff, c[s * 4 + k], fi * fg);
                        float h = fo * fast_tanh(c[s * 4 + k]);
                        int iSelf  = rowIdx[s] + (par ^ 1) * 896 + 1 + u;
                        int iChild = childIdx[s] + par * 1664 + u;
                        smem[iSelf]  = h; st_cluster_f32(peer_u32 + iSelf * 4, h);
                        smem[iChild] = h; st_cluster_f32(peer_u32 + iChild * 4, h);
                    }
                } else {
                    ulonglong2 V[13];
                    const ulonglong2* src = (const ulonglong2*)(smem + rowIdx[s] + par * 1664);
#pragma unroll
                    for (int ch = 0; ch < 13; ++ch) V[ch] = src[ch];
#pragma unroll
                    for (int k = 0; k < 4; ++k) if (k < nu) {
                        const int u = first + k;
                        const float* wr = smem + W123_OFF + (layer - 1) * 5200 + u * 52;
                        float4 bb = *(const float4*)(biasS + u * 4);
                        float s0, s1, s2, s3;
                        gates4reg<13>(V, wr, wr + 1300, wr + 2600, wr + 3900,
                                      bb.x, bb.y, bb.z, bb.w, s0, s1, s2, s3);
                        float fi = fast_sig(s0), ff = fast_sig(s1);
                        float fg = fast_tanh(s2), fo = fast_sig(s3);
                        c[s * 4 + k] = fmaf(ff, c[s * 4 + k], fi * fg);
                        float h = fo * fast_tanh(c[s * 4 + k]);
                        int iSelf = rowIdx[s] + (par ^ 1) * 1664 + 26 + u;
                        smem[iSelf] = h; st_cluster_f32(peer_u32 + iSelf * 4, h);
                        if (layer < 3) {
                            int iChild = childIdx[s] + par * 1664 + u;
                            smem[iChild] = h; st_cluster_f32(peer_u32 + iChild * 4, h);
                        }
                    }
                }
            }
        }
        cluster_arrive();   // release: local + remote SMEM writes visible after wait
        cluster_wait();
    }

    // ---- final states (h1,c1,h2,c2,h3,c3,h4,c4), each [4096,25]; owned units only ----
    if (write_states) {
        size_t base = (size_t)Tlen * NB;
        const size_t S = (size_t)NB * 25;
#pragma unroll
        for (int s = 0; s < 2; ++s) {
#pragma unroll
            for (int k = 0; k < 4; ++k) if (k < nu) {
                const int u = first + k;
                size_t idx = (size_t)gbS[s] * 25 + u;
                float h = (layer == 0) ? smem[rowIdx[s] + 1 + u]       // buffer 0
                                       : smem[rowIdx[s] + 26 + u];     // buffer 0
                out[base + (size_t)(2 * layer) * S + idx]     = h;
                out[base + (size_t)(2 * layer + 1) * S + idx] = c[s * 4 + k];
            }
        }
    }
}

extern "C" void kernel_launch(void* const* d_in, const int* in_sizes, int n_in,
                              void* d_out, int out_size) {
    (void)n_in; (void)in_sizes;
    const float* x    = (const float*)d_in[0];
    const float* Wih1 = (const float*)d_in[1];
    const float* Whh1 = (const float*)d_in[2];
    const float* bih1 = (const float*)d_in[3];
    const float* bhh1 = (const float*)d_in[4];
    const float* Wih2 = (const float*)d_in[5];
    const float* Whh2 = (const float*)d_in[6];
    const float* bih2 = (const float*)d_in[7];
    const float* bhh2 = (const float*)d_in[8];
    const float* Wih3 = (const float*)d_in[9];
    const float* Whh3 = (const float*)d_in[10];
    const float* bih3 = (const float*)d_in[11];
    const float* bhh3 = (const float*)d_in[12];
    const float* Wih4 = (const float*)d_in[13];
    const float* Whh4 = (const float*)d_in[14];
    const float* bih4 = (const float*)d_in[15];
    const float* bhh4 = (const float*)d_in[16];
    const float* Wfc  = (const float*)d_in[17];
    const float* bfc  = (const float*)d_in[18];

    int smem_bytes = SMEM_FLOATS * (int)sizeof(float);
    static int configured = -1;
    if (configured != smem_bytes) {
        cudaFuncSetAttribute(lstm_kernel,
                             cudaFuncAttributeMaxDynamicSharedMemorySize, smem_bytes);
        configured = smem_bytes;
    }
    int write_states = (out_size >= Tlen * NB + 8 * NB * 25) ? 1 : 0;

    // 64 clusters x 2 CTAs; each cluster owns 64 batch elements
    lstm_kernel<<<(NB / 64) * CLU, NTHR, smem_bytes>>>(
        x, Wih1, Whh1, bih1, bhh1,
        Wih2, Whh2, bih2, bhh2,
        Wih3, Whh3, bih3, bhh3,
        Wih4, Whh4, bih4, bhh4,
        Wfc, bfc, (float*)d_out, write_states);
}

// round 11
// speedup vs baseline: 1.6766x; 1.6766x over previous
#include <cuda_runtime.h>
#include <cstdint>
#include <cstddef>

typedef unsigned long long ull;

#define Tlen   512
#define NB     4096
#define NTHR   320          // w0-7: MMA (layer=w>>1, mt=w&1); w8: x-stager; w9: fc
#define NTICKS (Tlen + 4)

// smem float offsets
#define WB0_OFF   0                    // [13nt][4kt][2pass][64] = 6656
#define WB123_OFF 6656                 // 3 x [13][7][2][64] = 34944
#define BIAS_OFF  41600                // [4][104] fragment-col order
#define WFC_OFF   42016                // 64 (W_fc at [28..52])
#define V0_OFF    42080                // [2buf][32row][36] = 2304
#define V123_OFF  44384                // [3layer][2buf][32row][60] = 11520
#define SMEM_FLOATS 55904              // 223616 bytes

__device__ __forceinline__ ull pack2(float lo, float hi) {
    return (ull)__float_as_uint(lo) | ((ull)__float_as_uint(hi) << 32);
}
__device__ __forceinline__ float hsum2(ull v) {
    return __uint_as_float((unsigned)v) + __uint_as_float((unsigned)(v >> 32));
}
__device__ __forceinline__ void fma2(ull& acc, ull a, ull b) {
    asm("fma.rn.f32x2 %0, %1, %2, %0;" : "+l"(acc) : "l"(a), "l"(b));
}
__device__ __forceinline__ float fast_sig(float x) {
    float e, r;
    asm("ex2.approx.ftz.f32 %0, %1;" : "=f"(e) : "f"(x * -1.4426950408889634f));
    asm("rcp.approx.ftz.f32 %0, %1;" : "=f"(r) : "f"(e + 1.0f));
    return r;
}
__device__ __forceinline__ float fast_tanh(float x) {
    return fmaf(2.0f, fast_sig(2.0f * x), -1.0f);
}
__device__ __forceinline__ float tf_hi(float v) {
    return __uint_as_float(__float_as_uint(v) & 0xFFFFE000u);
}
__device__ __forceinline__ void mma8(float& d0, float& d1, float& d2, float& d3,
                                     float a0, float a1, float a2, float a3,
                                     float b0, float b1) {
    asm("mma.sync.aligned.m16n8k8.row.col.f32.tf32.tf32.f32 "
        "{%0,%1,%2,%3},{%4,%5,%6,%7},{%8,%9},{%0,%1,%2,%3};"
        : "+f"(d0), "+f"(d1), "+f"(d2), "+f"(d3)
        : "r"(__float_as_uint(a0)), "r"(__float_as_uint(a1)),
          "r"(__float_as_uint(a2)), "r"(__float_as_uint(a3)),
          "r"(__float_as_uint(b0)), "r"(__float_as_uint(b1)));
}

// one layer-tick for one MMA warp: D = V * W  (+bias), LSTM epilogue
template<int KT, int ROWW, int SELFC>
__device__ __forceinline__ void layer_tick(
    const float* __restrict__ vr, float* __restrict__ vself,
    float* __restrict__ vchild, const float* __restrict__ wb,
    const float* __restrict__ biasL, float* __restrict__ cst,
    int lane, int rA)
{
    const int c4 = lane & 3;
    const int podd = c4 & 1;
    const float kmul = podd ? 2.f : 1.f, kadd = podd ? -1.f : 0.f;

    float ah[KT][4], al[KT][4];
#pragma unroll
    for (int kt = 0; kt < KT; ++kt) {
        int k0 = kt * 8 + c4;
        float a0 = vr[rA * ROWW + k0];
        float a1 = vr[(rA + 8) * ROWW + k0];
        float a2 = vr[rA * ROWW + k0 + 4];
        float a3 = vr[(rA + 8) * ROWW + k0 + 4];
        ah[kt][0] = tf_hi(a0); al[kt][0] = a0 - ah[kt][0];
        ah[kt][1] = tf_hi(a1); al[kt][1] = a1 - ah[kt][1];
        ah[kt][2] = tf_hi(a2); al[kt][2] = a2 - ah[kt][2];
        ah[kt][3] = tf_hi(a3); al[kt][3] = a3 - ah[kt][3];
    }
#pragma unroll
    for (int nt = 0; nt < 13; ++nt) {
        float2 bb = *(const float2*)(biasL + nt * 8 + 2 * c4);
        float d0 = bb.x, d1 = bb.y, d2 = bb.x, d3 = bb.y;
        const float* wp = wb + nt * KT * 128;
#pragma unroll
        for (int kt = 0; kt < KT; ++kt) {
            float2 bh = *(const float2*)(wp + kt * 128 + lane * 2);
            float2 bl = *(const float2*)(wp + kt * 128 + 64 + lane * 2);
            mma8(d0, d1, d2, d3, ah[kt][0], ah[kt][1], ah[kt][2], ah[kt][3], bh.x, bh.y);
            mma8(d0, d1, d2, d3, al[kt][0], al[kt][1], al[kt][2], al[kt][3], bh.x, bh.y);
            mma8(d0, d1, d2, d3, ah[kt][0], ah[kt][1], ah[kt][2], ah[kt][3], bl.x, bl.y);
        }
        // epilogue: cols (2c4,2c4+1) = even c4:(i,f) / odd c4:(g,o) of unit u
        const int u = 2 * nt + (c4 >> 1);
        float a0 = fmaf(kmul, fast_sig(kmul * d0), kadd);
        float a1 = fast_sig(d1);
        float a2 = fmaf(kmul, fast_sig(kmul * d2), kadd);
        float a3 = fast_sig(d3);
        float x0 = __shfl_xor_sync(0xFFFFFFFFu, a0, 1);
        float x1 = __shfl_xor_sync(0xFFFFFFFFu, a1, 1);
        float x2 = __shfl_xor_sync(0xFFFFFFFFu, a2, 1);
        float x3 = __shfl_xor_sync(0xFFFFFFFFu, a3, 1);
        float i0 = podd ? x0 : a0, f0 = podd ? x1 : a1;
        float g0 = podd ? a0 : x0, o0 = podd ? a1 : x1;
        float i1 = podd ? x2 : a2, f1 = podd ? x3 : a3;
        float g1 = podd ? a2 : x2, o1 = podd ? a3 : x3;
        float c0 = fmaf(f0, cst[nt * 2 + 0], i0 * g0);
        float c1 = fmaf(f1, cst[nt * 2 + 1], i1 * g1);
        float h0 = o0 * fast_tanh(c0);
        float h1 = o1 * fast_tanh(c1);
        if (u < 25) {
            cst[nt * 2 + 0] = c0; cst[nt * 2 + 1] = c1;
            if (!podd) {
                vself[rA * ROWW + SELFC + u]       = h0;
                vself[(rA + 8) * ROWW + SELFC + u] = h1;
            } else if (vchild) {
                vchild[rA * 60 + u]       = h0;
                vchild[(rA + 8) * 60 + u] = h1;
            }
        }
    }
}

__global__ void __launch_bounds__(NTHR) lstm_kernel(
    const float* __restrict__ x,
    const float* __restrict__ Wih1, const float* __restrict__ Whh1,
    const float* __restrict__ bih1, const float* __restrict__ bhh1,
    const float* __restrict__ Wih2, const float* __restrict__ Whh2,
    const float* __restrict__ bih2, const float* __restrict__ bhh2,
    const float* __restrict__ Wih3, const float* __restrict__ Whh3,
    const float* __restrict__ bih3, const float* __restrict__ bhh3,
    const float* __restrict__ Wih4, const float* __restrict__ Whh4,
    const float* __restrict__ bih4, const float* __restrict__ bhh4,
    const float* __restrict__ Wfc, const float* __restrict__ bfc,
    float* __restrict__ out, int write_states)
{
    extern __shared__ float smem[];
    const int tid = threadIdx.x, lane = tid & 31, wid = tid >> 5;
    const int gb0 = blockIdx.x * 32;
    const float* WihL[4] = {Wih1, Wih2, Wih3, Wih4};
    const float* WhhL[4] = {Whh1, Whh2, Whh3, Whh4};
    const float* bihL[4] = {bih1, bih2, bih3, bih4};
    const float* bhhL[4] = {bhh1, bhh2, bhh3, bhh4};

    // ---- stage B fragments (hi at pass 0, lo at pass 1) ----
    // frag elem (lane,j): krel=(lane&3)+4j, local col lc=lane>>2, u=2nt+(lc>>2), gate=lc&3
    for (int i = tid; i < 6656; i += NTHR) {           // layer 1, KT=4, K=32
        int nt = i >> 9, r = i & 511, kt = r >> 7, r2 = r & 127;
        int pass = r2 >> 6, e = r2 & 63, ln = e >> 1, j = e & 1;
        int lc = ln >> 2, u = 2 * nt + (lc >> 2), gate = lc & 3;
        int k = kt * 8 + (ln & 3) + 4 * j;
        float w = 0.f;
        if (u < 25) {
            int row = gate * 25 + u;
            if (k == 0)       w = Wih1[row];
            else if (k <= 25) w = Whh1[row * 25 + k - 1];
        }
        float hi = tf_hi(w);
        smem[WB0_OFF + i] = pass ? (w - hi) : hi;
    }
    for (int i = tid; i < 34944; i += NTHR) {          // layers 2-4, KT=7, K=56
        int l = i / 11648, r0 = i - l * 11648;
        int nt = r0 / 896, r = r0 - nt * 896, kt = r >> 7, r2 = r & 127;
        int pass = r2 >> 6, e = r2 & 63, ln = e >> 1, j = e & 1;
        int lc = ln >> 2, u = 2 * nt + (lc >> 2), gate = lc & 3;
        int k = kt * 8 + (ln & 3) + 4 * j;
        float w = 0.f;
        if (u < 25) {
            int row = gate * 25 + u;
            if (k <= 24)                 w = WihL[l + 1][row * 25 + k];
            else if (k >= 28 && k <= 52) w = WhhL[l + 1][row * 25 + k - 28];
        }
        float hi = tf_hi(w);
        smem[WB123_OFF + i] = pass ? (w - hi) : hi;
    }
    for (int i = tid; i < 416; i += NTHR) {            // bias, fragment col order
        int l = i / 104, c = i - l * 104;
        int u = 2 * (c >> 3) + ((c & 7) >> 2), gate = c & 3;
        smem[BIAS_OFF + i] = (u < 25) ? (bihL[l][gate * 25 + u] + bhhL[l][gate * 25 + u]) : 0.f;
    }
    for (int i = tid; i < 64; i += NTHR)
        smem[WFC_OFF + i] = (i >= 28 && i < 53) ? Wfc[i - 28] : 0.f;
    for (int i = tid; i < 2304 + 11520; i += NTHR) smem[V0_OFF + i] = 0.f;

    const int layer = wid >> 1, mt = wid & 1;
    const int rA = mt * 16 + (lane >> 2);              // batch rows rA, rA+8

    float xreg = 0.f, bfc_reg = 0.f;
    if (wid == 8) {
        smem[V0_OFF + lane * 36] = x[gb0 + lane];      // x(0) -> buf 0
        xreg = x[(size_t)NB + gb0 + lane];
    }
    if (wid == 9) bfc_reg = bfc[0];
    __syncthreads();

    float cst[26];
#pragma unroll
    for (int i = 0; i < 26; ++i) cst[i] = 0.f;

    for (int T = 0; T < NTICKS; ++T) {
        if (wid == 8) {                                // x stager
            smem[V0_OFF + ((T + 1) & 1) * 1152 + lane * 36] = xreg;
            int t2 = (T + 2 < Tlen) ? T + 2 : Tlen - 1;
            xreg = x[(size_t)t2 * NB + gb0 + lane];
        }
        if (wid == 9 && T >= 4) {                      // fc: y(T-4)
            const ulonglong2* V3 = (const ulonglong2*)(smem + V123_OFF + 2 * 3840
                                   + ((T + 1) & 1) * 1920 + lane * 60);
            const ulonglong2* WF = (const ulonglong2*)(smem + WFC_OFF);
            ull A = pack2(bfc_reg, 0.f), B = 0ull;
#pragma unroll
            for (int ch = 7; ch < 14; ++ch) {          // floats 28..55 cover [28..52]
                ulonglong2 hv = V3[ch]; ulonglong2 w = WF[ch];
                fma2(A, w.x, hv.x); fma2(B, w.y, hv.y);
            }
            out[(size_t)(T - 4) * NB + gb0 + lane] = hsum2(A) + hsum2(B);
        }
        if (wid < 8 && T >= layer && T - layer < Tlen) {
            const int par = (T + layer) & 1;
            if (layer == 0) {
                layer_tick<4, 36, 1>(
                    smem + V0_OFF + par * 1152,
                    smem + V0_OFF + (par ^ 1) * 1152,
                    smem + V123_OFF + par * 1920,
                    smem + WB0_OFF, smem + BIAS_OFF, cst, lane, rA);
            } else {
                layer_tick<7, 60, 28>(
                    smem + V123_OFF + (layer - 1) * 3840 + par * 1920,
                    smem + V123_OFF + (layer - 1) * 3840 + (par ^ 1) * 1920,
                    (layer < 3) ? smem + V123_OFF + layer * 3840 + par * 1920 : (float*)0,
                    smem + WB123_OFF + (layer - 1) * 11648,
                    smem + BIAS_OFF + layer * 104, cst, lane, rA);
            }
        }
        __syncthreads();
    }

    // ---- final states: h from buf0 self slots, c from registers ----
    if (write_states && wid < 8 && !(lane & 1)) {      // even c4 lanes
        size_t base = (size_t)Tlen * NB;
        const size_t S = (size_t)NB * 25;
        const int roww  = (layer == 0) ? 36 : 60;
        const int selfc = (layer == 0) ? 1 : 28;
        const float* vb0 = (layer == 0) ? smem + V0_OFF
                          : smem + V123_OFF + (layer - 1) * 3840;
#pragma unroll
        for (int nt = 0; nt < 13; ++nt) {
            int u = 2 * nt + ((lane & 3) >> 1);
            if (u < 25) {
#pragma unroll
                for (int r2 = 0; r2 < 2; ++r2) {
                    int row = rA + 8 * r2;
                    size_t idx = (size_t)(gb0 + row) * 25 + u;
                    out[base + (size_t)(2 * layer) * S + idx]     = vb0[row * roww + selfc + u];
                    out[base + (size_t)(2 * layer + 1) * S + idx] = cst[nt * 2 + r2];
                }
            }
        }
    }
}

extern "C" void kernel_launch(void* const* d_in, const int* in_sizes, int n_in,
                              void* d_out, int out_size) {
    (void)n_in; (void)in_sizes;
    const float* a[19];
    for (int i = 0; i < 19; ++i) a[i] = (const float*)d_in[i];
    int smem_bytes = SMEM_FLOATS * (int)sizeof(float);
    static int configured = -1;
    if (configured != smem_bytes) {
        cudaFuncSetAttribute(lstm_kernel,
                             cudaFuncAttributeMaxDynamicSharedMemorySize, smem_bytes);
        configured = smem_bytes;
    }
    int write_states = (out_size >= Tlen * NB + 8 * NB * 25) ? 1 : 0;
    lstm_kernel<<<NB / 32, NTHR, smem_bytes>>>(
        a[0], a[1], a[2], a[3], a[4], a[5], a[6], a[7], a[8], a[9],
        a[10], a[11], a[12], a[13], a[14], a[15], a[16], a[17], a[18],
        (float*)d_out, write_states);
}

// round 12
// speedup vs baseline: 1.9709x; 1.1755x over previous
#include <cuda_runtime.h>
#include <cstdint>
#include <cstddef>

typedef unsigned long long ull;

#define Tlen   512
#define NB     4096
#define NTHR   320          // w0-7: MMA (layer=w>>1, mt=w&1); w8: x-stager; w9: fc
#define NTICKS (Tlen + 4)

// smem float offsets
#define WB0_OFF   0                    // [13nt][4kt][2pass][64] = 6656
#define WB123_OFF 6656                 // 3 x [13][7][2][64] = 34944
#define BIAS_OFF  41600                // [4][104] fragment-col order
#define WFC_OFF   42016                // 64 (W_fc at [28..52])
#define V0_OFF    42080                // [2buf][32row][36] = 2304
#define V123_OFF  44384                // [3layer][2buf][32row][60] = 11520
#define SMEM_FLOATS 55904              // 223616 bytes

__device__ __forceinline__ ull pack2(float lo, float hi) {
    return (ull)__float_as_uint(lo) | ((ull)__float_as_uint(hi) << 32);
}
__device__ __forceinline__ float hsum2(ull v) {
    return __uint_as_float((unsigned)v) + __uint_as_float((unsigned)(v >> 32));
}
__device__ __forceinline__ void fma2(ull& acc, ull a, ull b) {
    asm("fma.rn.f32x2 %0, %1, %2, %0;" : "+l"(acc) : "l"(a), "l"(b));
}
__device__ __forceinline__ float fast_sig(float x) {
    float e, r;
    asm("ex2.approx.ftz.f32 %0, %1;" : "=f"(e) : "f"(x * -1.4426950408889634f));
    asm("rcp.approx.ftz.f32 %0, %1;" : "=f"(r) : "f"(e + 1.0f));
    return r;
}
__device__ __forceinline__ float fast_tanh(float x) {
    return fmaf(2.0f, fast_sig(2.0f * x), -1.0f);
}
__device__ __forceinline__ float tf_hi(float v) {
    return __uint_as_float(__float_as_uint(v) & 0xFFFFE000u);
}
__device__ __forceinline__ void mma8(float& d0, float& d1, float& d2, float& d3,
                                     float a0, float a1, float a2, float a3,
                                     float b0, float b1) {
    asm("mma.sync.aligned.m16n8k8.row.col.f32.tf32.tf32.f32 "
        "{%0,%1,%2,%3},{%4,%5,%6,%7},{%8,%9},{%0,%1,%2,%3};"
        : "+f"(d0), "+f"(d1), "+f"(d2), "+f"(d3)
        : "r"(__float_as_uint(a0)), "r"(__float_as_uint(a1)),
          "r"(__float_as_uint(a2)), "r"(__float_as_uint(a3)),
          "r"(__float_as_uint(b0)), "r"(__float_as_uint(b1)));
}

// one layer-tick for one MMA warp: D = V * W (+bias), LSTM epilogue.
// nt-tiles processed in PAIRS; per nt the 3xTF32 accumulation is split into
// two independent chains (hi*hi | corrections) to expose HMMA ILP.
template<int KT, int ROWW, int SELFC>
__device__ __forceinline__ void layer_tick(
    const float* __restrict__ vr, float* __restrict__ vself,
    float* __restrict__ vchild, const float* __restrict__ wb,
    const float* __restrict__ biasL, float* __restrict__ cst,
    int lane, int rA)
{
    const int c4 = lane & 3;
    const int podd = c4 & 1;
    const float kmul = podd ? 2.f : 1.f, kadd = podd ? -1.f : 0.f;

    float ah[KT][4], al[KT][4];
#pragma unroll
    for (int kt = 0; kt < KT; ++kt) {
        int k0 = kt * 8 + c4;
        float a0 = vr[rA * ROWW + k0];
        float a1 = vr[(rA + 8) * ROWW + k0];
        float a2 = vr[rA * ROWW + k0 + 4];
        float a3 = vr[(rA + 8) * ROWW + k0 + 4];
        ah[kt][0] = tf_hi(a0); al[kt][0] = a0 - ah[kt][0];
        ah[kt][1] = tf_hi(a1); al[kt][1] = a1 - ah[kt][1];
        ah[kt][2] = tf_hi(a2); al[kt][2] = a2 - ah[kt][2];
        ah[kt][3] = tf_hi(a3); al[kt][3] = a3 - ah[kt][3];
    }

#pragma unroll
    for (int ntp = 0; ntp < 7; ++ntp) {
        const int nt0 = 2 * ntp;
        const int nt1 = 2 * ntp + 1;
        const bool has1 = (nt1 < 13);

        float2 bb0 = *(const float2*)(biasL + nt0 * 8 + 2 * c4);
        float eA0 = bb0.x, eA1 = bb0.y, eA2 = bb0.x, eA3 = bb0.y;   // chain A (hi*hi)
        float eB0 = 0.f, eB1 = 0.f, eB2 = 0.f, eB3 = 0.f;           // chain B (corr)
        float fA0 = 0.f, fA1 = 0.f, fA2 = 0.f, fA3 = 0.f;
        float fB0 = 0.f, fB1 = 0.f, fB2 = 0.f, fB3 = 0.f;
        if (has1) {
            float2 bb1 = *(const float2*)(biasL + nt1 * 8 + 2 * c4);
            fA0 = bb1.x; fA1 = bb1.y; fA2 = bb1.x; fA3 = bb1.y;
        }
        const float* wp0 = wb + nt0 * KT * 128;
        const float* wp1 = wb + nt1 * KT * 128;
#pragma unroll
        for (int kt = 0; kt < KT; ++kt) {
            float2 bh0 = *(const float2*)(wp0 + kt * 128 + lane * 2);
            float2 bl0 = *(const float2*)(wp0 + kt * 128 + 64 + lane * 2);
            mma8(eA0, eA1, eA2, eA3, ah[kt][0], ah[kt][1], ah[kt][2], ah[kt][3], bh0.x, bh0.y);
            mma8(eB0, eB1, eB2, eB3, al[kt][0], al[kt][1], al[kt][2], al[kt][3], bh0.x, bh0.y);
            if (has1) {
                float2 bh1 = *(const float2*)(wp1 + kt * 128 + lane * 2);
                float2 bl1 = *(const float2*)(wp1 + kt * 128 + 64 + lane * 2);
                mma8(fA0, fA1, fA2, fA3, ah[kt][0], ah[kt][1], ah[kt][2], ah[kt][3], bh1.x, bh1.y);
                mma8(fB0, fB1, fB2, fB3, al[kt][0], al[kt][1], al[kt][2], al[kt][3], bh1.x, bh1.y);
                mma8(fB0, fB1, fB2, fB3, ah[kt][0], ah[kt][1], ah[kt][2], ah[kt][3], bl1.x, bl1.y);
            }
            mma8(eB0, eB1, eB2, eB3, ah[kt][0], ah[kt][1], ah[kt][2], ah[kt][3], bl0.x, bl0.y);
        }

#pragma unroll
        for (int q = 0; q < 2; ++q) {
            const int nt = q ? nt1 : nt0;
            if (q && !has1) break;
            float d0 = q ? (fA0 + fB0) : (eA0 + eB0);
            float d1 = q ? (fA1 + fB1) : (eA1 + eB1);
            float d2 = q ? (fA2 + fB2) : (eA2 + eB2);
            float d3 = q ? (fA3 + fB3) : (eA3 + eB3);
            // epilogue: cols (2c4,2c4+1) = even c4:(i,f) / odd c4:(g,o) of unit u
            const int u = 2 * nt + (c4 >> 1);
            float a0 = fmaf(kmul, fast_sig(kmul * d0), kadd);
            float a1 = fast_sig(d1);
            float a2 = fmaf(kmul, fast_sig(kmul * d2), kadd);
            float a3 = fast_sig(d3);
            float x0 = __shfl_xor_sync(0xFFFFFFFFu, a0, 1);
            float x1 = __shfl_xor_sync(0xFFFFFFFFu, a1, 1);
            float x2 = __shfl_xor_sync(0xFFFFFFFFu, a2, 1);
            float x3 = __shfl_xor_sync(0xFFFFFFFFu, a3, 1);
            float i0 = podd ? x0 : a0, f0 = podd ? x1 : a1;
            float g0 = podd ? a0 : x0, o0 = podd ? a1 : x1;
            float i1 = podd ? x2 : a2, f1 = podd ? x3 : a3;
            float g1 = podd ? a2 : x2, o1 = podd ? a3 : x3;
            float c0 = fmaf(f0, cst[nt * 2 + 0], i0 * g0);
            float c1 = fmaf(f1, cst[nt * 2 + 1], i1 * g1);
            float h0 = o0 * fast_tanh(c0);
            float h1 = o1 * fast_tanh(c1);
            if (u < 25) {
                cst[nt * 2 + 0] = c0; cst[nt * 2 + 1] = c1;
                if (!podd) {
                    vself[rA * ROWW + SELFC + u]       = h0;
                    vself[(rA + 8) * ROWW + SELFC + u] = h1;
                } else if (vchild) {
                    vchild[rA * 60 + u]       = h0;
                    vchild[(rA + 8) * 60 + u] = h1;
                }
            }
        }
    }
}

__global__ void __launch_bounds__(NTHR) lstm_kernel(
    const float* __restrict__ x,
    const float* __restrict__ Wih1, const float* __restrict__ Whh1,
    const float* __restrict__ bih1, const float* __restrict__ bhh1,
    const float* __restrict__ Wih2, const float* __restrict__ Whh2,
    const float* __restrict__ bih2, const float* __restrict__ bhh2,
    const float* __restrict__ Wih3, const float* __restrict__ Whh3,
    const float* __restrict__ bih3, const float* __restrict__ bhh3,
    const float* __restrict__ Wih4, const float* __restrict__ Whh4,
    const float* __restrict__ bih4, const float* __restrict__ bhh4,
    const float* __restrict__ Wfc, const float* __restrict__ bfc,
    float* __restrict__ out, int write_states)
{
    extern __shared__ float smem[];
    const int tid = threadIdx.x, lane = tid & 31, wid = tid >> 5;
    const int gb0 = blockIdx.x * 32;
    const float* WihL[4] = {Wih1, Wih2, Wih3, Wih4};
    const float* WhhL[4] = {Whh1, Whh2, Whh3, Whh4};
    const float* bihL[4] = {bih1, bih2, bih3, bih4};
    const float* bhhL[4] = {bhh1, bhh2, bhh3, bhh4};

    // ---- stage B fragments (hi at pass 0, lo at pass 1) ----
    for (int i = tid; i < 6656; i += NTHR) {           // layer 1, KT=4, K=32
        int nt = i >> 9, r = i & 511, kt = r >> 7, r2 = r & 127;
        int pass = r2 >> 6, e = r2 & 63, ln = e >> 1, j = e & 1;
        int lc = ln >> 2, u = 2 * nt + (lc >> 2), gate = lc & 3;
        int k = kt * 8 + (ln & 3) + 4 * j;
        float w = 0.f;
        if (u < 25) {
            int row = gate * 25 + u;
            if (k == 0)       w = Wih1[row];
            else if (k <= 25) w = Whh1[row * 25 + k - 1];
        }
        float hi = tf_hi(w);
        smem[WB0_OFF + i] = pass ? (w - hi) : hi;
    }
    for (int i = tid; i < 34944; i += NTHR) {          // layers 2-4, KT=7, K=56
        int l = i / 11648, r0 = i - l * 11648;
        int nt = r0 / 896, r = r0 - nt * 896, kt = r >> 7, r2 = r & 127;
        int pass = r2 >> 6, e = r2 & 63, ln = e >> 1, j = e & 1;
        int lc = ln >> 2, u = 2 * nt + (lc >> 2), gate = lc & 3;
        int k = kt * 8 + (ln & 3) + 4 * j;
        float w = 0.f;
        if (u < 25) {
            int row = gate * 25 + u;
            if (k <= 24)                 w = WihL[l + 1][row * 25 + k];
            else if (k >= 28 && k <= 52) w = WhhL[l + 1][row * 25 + k - 28];
        }
        float hi = tf_hi(w);
        smem[WB123_OFF + i] = pass ? (w - hi) : hi;
    }
    for (int i = tid; i < 416; i += NTHR) {            // bias, fragment col order
        int l = i / 104, c = i - l * 104;
        int u = 2 * (c >> 3) + ((c & 7) >> 2), gate = c & 3;
        smem[BIAS_OFF + i] = (u < 25) ? (bihL[l][gate * 25 + u] + bhhL[l][gate * 25 + u]) : 0.f;
    }
    for (int i = tid; i < 64; i += NTHR)
        smem[WFC_OFF + i] = (i >= 28 && i < 53) ? Wfc[i - 28] : 0.f;
    for (int i = tid; i < 2304 + 11520; i += NTHR) smem[V0_OFF + i] = 0.f;

    const int layer = wid >> 1, mt = wid & 1;
    const int rA = mt * 16 + (lane >> 2);              // batch rows rA, rA+8

    float xreg = 0.f, bfc_reg = 0.f;
    if (wid == 8) {
        smem[V0_OFF + lane * 36] = x[gb0 + lane];      // x(0) -> buf 0
        xreg = x[(size_t)NB + gb0 + lane];
    }
    if (wid == 9) bfc_reg = bfc[0];
    __syncthreads();

    float cst[26];
#pragma unroll
    for (int i = 0; i < 26; ++i) cst[i] = 0.f;

    for (int T = 0; T < NTICKS; ++T) {
        if (wid == 8) {                                // x stager
            smem[V0_OFF + ((T + 1) & 1) * 1152 + lane * 36] = xreg;
            int t2 = (T + 2 < Tlen) ? T + 2 : Tlen - 1;
            xreg = x[(size_t)t2 * NB + gb0 + lane];
        }
        if (wid == 9 && T >= 4) {                      // fc: y(T-4)
            const ulonglong2* V3 = (const ulonglong2*)(smem + V123_OFF + 2 * 3840
                                   + ((T + 1) & 1) * 1920 + lane * 60);
            const ulonglong2* WF = (const ulonglong2*)(smem + WFC_OFF);
            ull A = pack2(bfc_reg, 0.f), B = 0ull;
#pragma unroll
            for (int ch = 7; ch < 14; ++ch) {          // floats 28..55 cover [28..52]
                ulonglong2 hv = V3[ch]; ulonglong2 w = WF[ch];
                fma2(A, w.x, hv.x); fma2(B, w.y, hv.y);
            }
            out[(size_t)(T - 4) * NB + gb0 + lane] = hsum2(A) + hsum2(B);
        }
        if (wid < 8 && T >= layer && T - layer < Tlen) {
            const int par = (T + layer) & 1;
            if (layer == 0) {
                layer_tick<4, 36, 1>(
                    smem + V0_OFF + par * 1152,
                    smem + V0_OFF + (par ^ 1) * 1152,
                    smem + V123_OFF + par * 1920,
                    smem + WB0_OFF, smem + BIAS_OFF, cst, lane, rA);
            } else {
                layer_tick<7, 60, 28>(
                    smem + V123_OFF + (layer - 1) * 3840 + par * 1920,
                    smem + V123_OFF + (layer - 1) * 3840 + (par ^ 1) * 1920,
                    (layer < 3) ? smem + V123_OFF + layer * 3840 + par * 1920 : (float*)0,
                    smem + WB123_OFF + (layer - 1) * 11648,
                    smem + BIAS_OFF + layer * 104, cst, lane, rA);
            }
        }
        __syncthreads();
    }

    // ---- final states: h from buf0 self slots, c from registers ----
    if (write_states && wid < 8 && !(lane & 1)) {      // even c4 lanes
        size_t base = (size_t)Tlen * NB;
        const size_t S = (size_t)NB * 25;
        const int roww  = (layer == 0) ? 36 : 60;
        const int selfc = (layer == 0) ? 1 : 28;
        const float* vb0 = (layer == 0) ? smem + V0_OFF
                          : smem + V123_OFF + (layer - 1) * 3840;
#pragma unroll
        for (int nt = 0; nt < 13; ++nt) {
            int u = 2 * nt + ((lane & 3) >> 1);
            if (u < 25) {
#pragma unroll
                for (int r2 = 0; r2 < 2; ++r2) {
                    int row = rA + 8 * r2;
                    size_t idx = (size_t)(gb0 + row) * 25 + u;
                    out[base + (size_t)(2 * layer) * S + idx]     = vb0[row * roww + selfc + u];
                    out[base + (size_t)(2 * layer + 1) * S + idx] = cst[nt * 2 + r2];
                }
            }
        }
    }
}

extern "C" void kernel_launch(void* const* d_in, const int* in_sizes, int n_in,
                              void* d_out, int out_size) {
    (void)n_in; (void)in_sizes;
    const float* a[19];
    for (int i = 0; i < 19; ++i) a[i] = (const float*)d_in[i];
    int smem_bytes = SMEM_FLOATS * (int)sizeof(float);
    static int configured = -1;
    if (configured != smem_bytes) {
        cudaFuncSetAttribute(lstm_kernel,
                             cudaFuncAttributeMaxDynamicSharedMemorySize, smem_bytes);
        configured = smem_bytes;
    }
    int write_states = (out_size >= Tlen * NB + 8 * NB * 25) ? 1 : 0;
    lstm_kernel<<<NB / 32, NTHR, smem_bytes>>>(
        a[0], a[1], a[2], a[3], a[4], a[5], a[6], a[7], a[8], a[9],
        a[10], a[11], a[12], a[13], a[14], a[15], a[16], a[17], a[18],
        (float*)d_out, write_states);
}

// round 13
// speedup vs baseline: 2.0839x; 1.0573x over previous
#include <cuda_runtime.h>
#include <cstdint>
#include <cstddef>

typedef unsigned long long ull;

#define Tlen   512
#define NB     4096
#define NTHR   576          // w0-15: MMA (layer=w>>2, mt=(w&3)>>1, nth=w&1); w16: stager; w17: fc
#define NTICKS (Tlen + 4)

// smem float offsets
#define WB0_OFF   0                    // [13nt][4kt][2pass][64] = 6656
#define WB123_OFF 6656                 // 3 x [13][7][2][64] = 34944
#define BIAS_OFF  41600                // [4][104] fragment-col order
#define WFC_OFF   42016                // 64 (W_fc at [28..52])
#define V0_OFF    42080                // [2buf][32row][36] = 2304
#define V123_OFF  44384                // [3layer][2buf][32row][60] = 11520
#define SMEM_FLOATS 55904              // 223616 bytes

__device__ __forceinline__ ull pack2(float lo, float hi) {
    return (ull)__float_as_uint(lo) | ((ull)__float_as_uint(hi) << 32);
}
__device__ __forceinline__ float hsum2(ull v) {
    return __uint_as_float((unsigned)v) + __uint_as_float((unsigned)(v >> 32));
}
__device__ __forceinline__ void fma2(ull& acc, ull a, ull b) {
    asm("fma.rn.f32x2 %0, %1, %2, %0;" : "+l"(acc) : "l"(a), "l"(b));
}
__device__ __forceinline__ float fast_sig(float x) {
    float e, r;
    asm("ex2.approx.ftz.f32 %0, %1;" : "=f"(e) : "f"(x * -1.4426950408889634f));
    asm("rcp.approx.ftz.f32 %0, %1;" : "=f"(r) : "f"(e + 1.0f));
    return r;
}
__device__ __forceinline__ float fast_tanh(float x) {
    return fmaf(2.0f, fast_sig(2.0f * x), -1.0f);
}
__device__ __forceinline__ float tf_hi(float v) {
    return __uint_as_float(__float_as_uint(v) & 0xFFFFE000u);
}
__device__ __forceinline__ void mma8(float& d0, float& d1, float& d2, float& d3,
                                     float a0, float a1, float a2, float a3,
                                     float b0, float b1) {
    asm("mma.sync.aligned.m16n8k8.row.col.f32.tf32.tf32.f32 "
        "{%0,%1,%2,%3},{%4,%5,%6,%7},{%8,%9},{%0,%1,%2,%3};"
        : "+f"(d0), "+f"(d1), "+f"(d2), "+f"(d3)
        : "r"(__float_as_uint(a0)), "r"(__float_as_uint(a1)),
          "r"(__float_as_uint(a2)), "r"(__float_as_uint(a3)),
          "r"(__float_as_uint(b0)), "r"(__float_as_uint(b1)));
}

// one layer-tick slice for one MMA warp: nt-tiles [NT0, NT0+NTN).
template<int KT, int ROWW, int SELFC, int NT0, int NTN>
__device__ __forceinline__ void layer_tick(
    const float* __restrict__ vr, float* __restrict__ vself,
    float* __restrict__ vchild, const float* __restrict__ wb,
    const float* __restrict__ biasL, float* __restrict__ cst,
    int lane, int rA)
{
    const int c4 = lane & 3;
    const int podd = c4 & 1;
    const float kmul = podd ? 2.f : 1.f, kadd = podd ? -1.f : 0.f;

    float ah[KT][4], al[KT][4];
#pragma unroll
    for (int kt = 0; kt < KT; ++kt) {
        int k0 = kt * 8 + c4;
        float a0 = vr[rA * ROWW + k0];
        float a1 = vr[(rA + 8) * ROWW + k0];
        float a2 = vr[rA * ROWW + k0 + 4];
        float a3 = vr[(rA + 8) * ROWW + k0 + 4];
        ah[kt][0] = tf_hi(a0); al[kt][0] = a0 - ah[kt][0];
        ah[kt][1] = tf_hi(a1); al[kt][1] = a1 - ah[kt][1];
        ah[kt][2] = tf_hi(a2); al[kt][2] = a2 - ah[kt][2];
        ah[kt][3] = tf_hi(a3); al[kt][3] = a3 - ah[kt][3];
    }

#pragma unroll
    for (int ntp = 0; ntp < (NTN + 1) / 2; ++ntp) {
        const int nt0 = NT0 + 2 * ntp;
        const int nt1 = nt0 + 1;
        const bool has1 = (nt1 < NT0 + NTN);

        float2 bb0 = *(const float2*)(biasL + nt0 * 8 + 2 * c4);
        float eA0 = bb0.x, eA1 = bb0.y, eA2 = bb0.x, eA3 = bb0.y;   // hi*hi chain
        float eB0 = 0.f, eB1 = 0.f, eB2 = 0.f, eB3 = 0.f;           // corrections
        float fA0 = 0.f, fA1 = 0.f, fA2 = 0.f, fA3 = 0.f;
        float fB0 = 0.f, fB1 = 0.f, fB2 = 0.f, fB3 = 0.f;
        if (has1) {
            float2 bb1 = *(const float2*)(biasL + nt1 * 8 + 2 * c4);
            fA0 = bb1.x; fA1 = bb1.y; fA2 = bb1.x; fA3 = bb1.y;
        }
        const float* wp0 = wb + nt0 * KT * 128;
        const float* wp1 = wb + nt1 * KT * 128;
#pragma unroll
        for (int kt = 0; kt < KT; ++kt) {
            float2 bh0 = *(const float2*)(wp0 + kt * 128 + lane * 2);
            float2 bl0 = *(const float2*)(wp0 + kt * 128 + 64 + lane * 2);
            mma8(eA0, eA1, eA2, eA3, ah[kt][0], ah[kt][1], ah[kt][2], ah[kt][3], bh0.x, bh0.y);
            mma8(eB0, eB1, eB2, eB3, al[kt][0], al[kt][1], al[kt][2], al[kt][3], bh0.x, bh0.y);
            if (has1) {
                float2 bh1 = *(const float2*)(wp1 + kt * 128 + lane * 2);
                float2 bl1 = *(const float2*)(wp1 + kt * 128 + 64 + lane * 2);
                mma8(fA0, fA1, fA2, fA3, ah[kt][0], ah[kt][1], ah[kt][2], ah[kt][3], bh1.x, bh1.y);
                mma8(fB0, fB1, fB2, fB3, al[kt][0], al[kt][1], al[kt][2], al[kt][3], bh1.x, bh1.y);
                mma8(fB0, fB1, fB2, fB3, ah[kt][0], ah[kt][1], ah[kt][2], ah[kt][3], bl1.x, bl1.y);
            }
            mma8(eB0, eB1, eB2, eB3, ah[kt][0], ah[kt][1], ah[kt][2], ah[kt][3], bl0.x, bl0.y);
        }

#pragma unroll
        for (int q = 0; q < 2; ++q) {
            const int nt = q ? nt1 : nt0;
            if (q && !has1) break;
            float d0 = q ? (fA0 + fB0) : (eA0 + eB0);
            float d1 = q ? (fA1 + fB1) : (eA1 + eB1);
            float d2 = q ? (fA2 + fB2) : (eA2 + eB2);
            float d3 = q ? (fA3 + fB3) : (eA3 + eB3);
            const int u = 2 * nt + (c4 >> 1);
            float a0 = fmaf(kmul, fast_sig(kmul * d0), kadd);
            float a1 = fast_sig(d1);
            float a2 = fmaf(kmul, fast_sig(kmul * d2), kadd);
            float a3 = fast_sig(d3);
            float x0 = __shfl_xor_sync(0xFFFFFFFFu, a0, 1);
            float x1 = __shfl_xor_sync(0xFFFFFFFFu, a1, 1);
            float x2 = __shfl_xor_sync(0xFFFFFFFFu, a2, 1);
            float x3 = __shfl_xor_sync(0xFFFFFFFFu, a3, 1);
            float i0 = podd ? x0 : a0, f0 = podd ? x1 : a1;
            float g0 = podd ? a0 : x0, o0 = podd ? a1 : x1;
            float i1 = podd ? x2 : a2, f1 = podd ? x3 : a3;
            float g1 = podd ? a2 : x2, o1 = podd ? a3 : x3;
            const int ci = (nt - NT0) * 2;
            float c0 = fmaf(f0, cst[ci + 0], i0 * g0);
            float c1 = fmaf(f1, cst[ci + 1], i1 * g1);
            float h0 = o0 * fast_tanh(c0);
            float h1 = o1 * fast_tanh(c1);
            if (u < 25) {
                cst[ci + 0] = c0; cst[ci + 1] = c1;
                if (!podd) {
                    vself[rA * ROWW + SELFC + u]       = h0;
                    vself[(rA + 8) * ROWW + SELFC + u] = h1;
                } else if (vchild) {
                    vchild[rA * 60 + u]       = h0;
                    vchild[(rA + 8) * 60 + u] = h1;
                }
            }
        }
    }
}

__global__ void __launch_bounds__(NTHR) lstm_kernel(
    const float* __restrict__ x,
    const float* __restrict__ Wih1, const float* __restrict__ Whh1,
    const float* __restrict__ bih1, const float* __restrict__ bhh1,
    const float* __restrict__ Wih2, const float* __restrict__ Whh2,
    const float* __restrict__ bih2, const float* __restrict__ bhh2,
    const float* __restrict__ Wih3, const float* __restrict__ Whh3,
    const float* __restrict__ bih3, const float* __restrict__ bhh3,
    const float* __restrict__ Wih4, const float* __restrict__ Whh4,
    const float* __restrict__ bih4, const float* __restrict__ bhh4,
    const float* __restrict__ Wfc, const float* __restrict__ bfc,
    float* __restrict__ out, int write_states)
{
    extern __shared__ float smem[];
    const int tid = threadIdx.x, lane = tid & 31, wid = tid >> 5;
    const int gb0 = blockIdx.x * 32;
    const float* WihL[4] = {Wih1, Wih2, Wih3, Wih4};
    const float* WhhL[4] = {Whh1, Whh2, Whh3, Whh4};
    const float* bihL[4] = {bih1, bih2, bih3, bih4};
    const float* bhhL[4] = {bhh1, bhh2, bhh3, bhh4};

    // ---- stage B fragments (hi pass 0, lo pass 1) ----
    for (int i = tid; i < 6656; i += NTHR) {           // layer 1, KT=4
        int nt = i >> 9, r = i & 511, kt = r >> 7, r2 = r & 127;
        int pass = r2 >> 6, e = r2 & 63, ln = e >> 1, j = e & 1;
        int lc = ln >> 2, u = 2 * nt + (lc >> 2), gate = lc & 3;
        int k = kt * 8 + (ln & 3) + 4 * j;
        float w = 0.f;
        if (u < 25) {
            int row = gate * 25 + u;
            if (k == 0)       w = Wih1[row];
            else if (k <= 25) w = Whh1[row * 25 + k - 1];
        }
        float hi = tf_hi(w);
        smem[WB0_OFF + i] = pass ? (w - hi) : hi;
    }
    for (int i = tid; i < 34944; i += NTHR) {          // layers 2-4, KT=7
        int l = i / 11648, r0 = i - l * 11648;
        int nt = r0 / 896, r = r0 - nt * 896, kt = r >> 7, r2 = r & 127;
        int pass = r2 >> 6, e = r2 & 63, ln = e >> 1, j = e & 1;
        int lc = ln >> 2, u = 2 * nt + (lc >> 2), gate = lc & 3;
        int k = kt * 8 + (ln & 3) + 4 * j;
        float w = 0.f;
        if (u < 25) {
            int row = gate * 25 + u;
            if (k <= 24)                 w = WihL[l + 1][row * 25 + k];
            else if (k >= 28 && k <= 52) w = WhhL[l + 1][row * 25 + k - 28];
        }
        float hi = tf_hi(w);
        smem[WB123_OFF + i] = pass ? (w - hi) : hi;
    }
    for (int i = tid; i < 416; i += NTHR) {
        int l = i / 104, c = i - l * 104;
        int u = 2 * (c >> 3) + ((c & 7) >> 2), gate = c & 3;
        smem[BIAS_OFF + i] = (u < 25) ? (bihL[l][gate * 25 + u] + bhhL[l][gate * 25 + u]) : 0.f;
    }
    for (int i = tid; i < 64; i += NTHR)
        smem[WFC_OFF + i] = (i >= 28 && i < 53) ? Wfc[i - 28] : 0.f;
    for (int i = tid; i < 2304 + 11520; i += NTHR) smem[V0_OFF + i] = 0.f;

    const int layer = wid >> 2, mt = (wid & 3) >> 1, nth = wid & 1;
    const int rA = mt * 16 + (lane >> 2);

    float xreg = 0.f, bfc_reg = 0.f;
    if (wid == 16) {
        smem[V0_OFF + lane * 36] = x[gb0 + lane];
        xreg = x[(size_t)NB + gb0 + lane];
    }
    if (wid == 17) bfc_reg = bfc[0];
    __syncthreads();

    float cst[14];
#pragma unroll
    for (int i = 0; i < 14; ++i) cst[i] = 0.f;

    for (int T = 0; T < NTICKS; ++T) {
        if (wid == 16) {                               // x stager
            smem[V0_OFF + ((T + 1) & 1) * 1152 + lane * 36] = xreg;
            int t2 = (T + 2 < Tlen) ? T + 2 : Tlen - 1;
            xreg = x[(size_t)t2 * NB + gb0 + lane];
        }
        if (wid == 17 && T >= 4) {                     // fc: y(T-4)
            const ulonglong2* V3 = (const ulonglong2*)(smem + V123_OFF + 2 * 3840
                                   + ((T + 1) & 1) * 1920 + lane * 60);
            const ulonglong2* WF = (const ulonglong2*)(smem + WFC_OFF);
            ull A = pack2(bfc_reg, 0.f), B = 0ull;
#pragma unroll
            for (int ch = 7; ch < 14; ++ch) {
                ulonglong2 hv = V3[ch]; ulonglong2 w = WF[ch];
                fma2(A, w.x, hv.x); fma2(B, w.y, hv.y);
            }
            out[(size_t)(T - 4) * NB + gb0 + lane] = hsum2(A) + hsum2(B);
        }
        if (wid < 16 && T >= layer && T - layer < Tlen) {
            const int par = (T + layer) & 1;
            if (layer == 0) {
                const float* vr = smem + V0_OFF + par * 1152;
                float* vs = smem + V0_OFF + (par ^ 1) * 1152;
                float* vc = smem + V123_OFF + par * 1920;
                if (nth == 0)
                    layer_tick<4, 36, 1, 0, 7>(vr, vs, vc, smem + WB0_OFF,
                                               smem + BIAS_OFF, cst, lane, rA);
                else
                    layer_tick<4, 36, 1, 7, 6>(vr, vs, vc, smem + WB0_OFF,
                                               smem + BIAS_OFF, cst, lane, rA);
            } else {
                const float* vr = smem + V123_OFF + (layer - 1) * 3840 + par * 1920;
                float* vs = smem + V123_OFF + (layer - 1) * 3840 + (par ^ 1) * 1920;
                float* vc = (layer < 3) ? smem + V123_OFF + layer * 3840 + par * 1920
                                        : (float*)0;
                const float* wb = smem + WB123_OFF + (layer - 1) * 11648;
                const float* bs = smem + BIAS_OFF + layer * 104;
                if (nth == 0)
                    layer_tick<7, 60, 28, 0, 7>(vr, vs, vc, wb, bs, cst, lane, rA);
                else
                    layer_tick<7, 60, 28, 7, 6>(vr, vs, vc, wb, bs, cst, lane, rA);
            }
        }
        __syncthreads();
    }

    // ---- final states ----
    if (write_states && wid < 16 && !(lane & 1)) {
        size_t base = (size_t)Tlen * NB;
        const size_t S = (size_t)NB * 25;
        const int roww  = (layer == 0) ? 36 : 60;
        const int selfc = (layer == 0) ? 1 : 28;
        const float* vb0 = (layer == 0) ? smem + V0_OFF
                          : smem + V123_OFF + (layer - 1) * 3840;
        const int ntlo = nth ? 7 : 0, nthi = nth ? 13 : 7;
        for (int nt = ntlo; nt < nthi; ++nt) {
            int u = 2 * nt + ((lane & 3) >> 1);
            if (u < 25) {
#pragma unroll
                for (int r2 = 0; r2 < 2; ++r2) {
                    int row = rA + 8 * r2;
                    size_t idx = (size_t)(gb0 + row) * 25 + u;
                    out[base + (size_t)(2 * layer) * S + idx]     = vb0[row * roww + selfc + u];
                    out[base + (size_t)(2 * layer + 1) * S + idx] = cst[(nt - ntlo) * 2 + r2];
                }
            }
        }
    }
}

extern "C" void kernel_launch(void* const* d_in, const int* in_sizes, int n_in,
                              void* d_out, int out_size) {
    (void)n_in; (void)in_sizes;
    const float* a[19];
    for (int i = 0; i < 19; ++i) a[i] = (const float*)d_in[i];
    int smem_bytes = SMEM_FLOATS * (int)sizeof(float);
    static int configured = -1;
    if (configured != smem_bytes) {
        cudaFuncSetAttribute(lstm_kernel,
                             cudaFuncAttributeMaxDynamicSharedMemorySize, smem_bytes);
        configured = smem_bytes;
    }
    int write_states = (out_size >= Tlen * NB + 8 * NB * 25) ? 1 : 0;
    lstm_kernel<<<NB / 32, NTHR, smem_bytes>>>(
        a[0], a[1], a[2], a[3], a[4], a[5], a[6], a[7], a[8], a[9],
        a[10], a[11], a[12], a[13], a[14], a[15], a[16], a[17], a[18],
        (float*)d_out, write_states);
}

// round 15
// speedup vs baseline: 2.1279x; 1.0212x over previous
#include <cuda_runtime.h>
#include <cstdint>
#include <cstddef>

typedef unsigned long long ull;

#define Tlen   512
#define NB     4096
#define NTHR   576          // w0-15: MMA (layer=w>>2, mt=(w&3)>>1, nth=w&1); w16: stager; w17: fc
#define NTICKS (Tlen + 4)

// interleaved column position: logical col k -> storage pos (pairs (k,k+4) adjacent)
#define COLPOS(k) (((k) & ~7) | ((((k) & 3) << 1) | (((k) >> 2) & 1)))

// smem float offsets
#define WB0_OFF   0                    // [13nt][4kt][2pass][64] = 6656
#define WB123_OFF 6656                 // 3 x [13][7][2][64] = 34944
#define BIAS_OFF  41600                // [4][104] fragment-col order
#define WFC_OFF   42016                // 64, interleaved positions
#define V0_OFF    42080                // [2buf][32row][36] = 2304
#define V123_OFF  44384                // [3layer][2buf][32row][60] = 11520
#define SMEM_FLOATS 55904              // 223616 bytes

__device__ __forceinline__ ull pack2(float lo, float hi) {
    return (ull)__float_as_uint(lo) | ((ull)__float_as_uint(hi) << 32);
}
__device__ __forceinline__ float hsum2(ull v) {
    return __uint_as_float((unsigned)v) + __uint_as_float((unsigned)(v >> 32));
}
__device__ __forceinline__ void fma2(ull& acc, ull a, ull b) {
    asm("fma.rn.f32x2 %0, %1, %2, %0;" : "+l"(acc) : "l"(a), "l"(b));
}
__device__ __forceinline__ float fast_sig(float x) {
    float e, r;
    asm("ex2.approx.ftz.f32 %0, %1;" : "=f"(e) : "f"(x * -1.4426950408889634f));
    asm("rcp.approx.ftz.f32 %0, %1;" : "=f"(r) : "f"(e + 1.0f));
    return r;
}
__device__ __forceinline__ float fast_tanh(float x) {
    return fmaf(2.0f, fast_sig(2.0f * x), -1.0f);
}
__device__ __forceinline__ float tf_hi(float v) {
    return __uint_as_float(__float_as_uint(v) & 0xFFFFE000u);
}
__device__ __forceinline__ void mma8(float& d0, float& d1, float& d2, float& d3,
                                     float a0, float a1, float a2, float a3,
                                     float b0, float b1) {
    asm("mma.sync.aligned.m16n8k8.row.col.f32.tf32.tf32.f32 "
        "{%0,%1,%2,%3},{%4,%5,%6,%7},{%8,%9},{%0,%1,%2,%3};"
        : "+f"(d0), "+f"(d1), "+f"(d2), "+f"(d3)
        : "r"(__float_as_uint(a0)), "r"(__float_as_uint(a1)),
          "r"(__float_as_uint(a2)), "r"(__float_as_uint(a3)),
          "r"(__float_as_uint(b0)), "r"(__float_as_uint(b1)));
}

// staging map: tile nt, local col lc -> (unit, gate). Pair layout for nt<12,
// old 2-unit layout for the special tile nt==12 (covers unit 24).
__device__ __forceinline__ void col_map(int nt, int lc, int& u, int& gidx) {
    if (nt < 12) { u = 4 * (nt >> 1) + (lc >> 1); gidx = ((nt & 1) << 1) | (lc & 1); }
    else         { u = 24 + (lc >> 2);            gidx = lc & 3; }
}

// one layer-tick slice: pairs [PAIR0, PAIR0+NPAIR) (+ special tile if SPEC).
template<int KT, int ROWW, int SELFC, int PAIR0, int NPAIR, int SPEC>
__device__ __forceinline__ void layer_tick(
    const float* __restrict__ vr, float* __restrict__ vself,
    float* __restrict__ vchild, const float* __restrict__ wb,
    const float* __restrict__ biasL, float* __restrict__ cst,
    int lane, int rA)
{
    const int c4 = lane & 3;

    float ah[KT][4], al[KT][4];
#pragma unroll
    for (int kt = 0; kt < KT; ++kt) {
        float2 p0 = *(const float2*)(vr + rA * ROWW + kt * 8 + 2 * c4);
        float2 p1 = *(const float2*)(vr + (rA + 8) * ROWW + kt * 8 + 2 * c4);
        ah[kt][0] = tf_hi(p0.x); al[kt][0] = p0.x - ah[kt][0];
        ah[kt][1] = tf_hi(p1.x); al[kt][1] = p1.x - ah[kt][1];
        ah[kt][2] = tf_hi(p0.y); al[kt][2] = p0.y - ah[kt][2];
        ah[kt][3] = tf_hi(p1.y); al[kt][3] = p1.y - ah[kt][3];
    }

#pragma unroll
    for (int pp = 0; pp < NPAIR; ++pp) {
        const int pa = PAIR0 + pp;
        const int nt0 = 2 * pa, nt1 = nt0 + 1;
        float2 bb0 = *(const float2*)(biasL + nt0 * 8 + 2 * c4);
        float2 bb1 = *(const float2*)(biasL + nt1 * 8 + 2 * c4);
        float eA0 = bb0.x, eA1 = bb0.y, eA2 = bb0.x, eA3 = bb0.y;  // (i,f) hi chain
        float eB0 = 0.f, eB1 = 0.f, eB2 = 0.f, eB3 = 0.f;          // (i,f) corr
        float fA0 = bb1.x, fA1 = bb1.y, fA2 = bb1.x, fA3 = bb1.y;  // (g,o) hi chain
        float fB0 = 0.f, fB1 = 0.f, fB2 = 0.f, fB3 = 0.f;          // (g,o) corr
        const float* wp0 = wb + nt0 * KT * 128;
        const float* wp1 = wb + nt1 * KT * 128;
#pragma unroll
        for (int kt = 0; kt < KT; ++kt) {
            float2 bh0 = *(const float2*)(wp0 + kt * 128 + lane * 2);
            float2 bl0 = *(const float2*)(wp0 + kt * 128 + 64 + lane * 2);
            float2 bh1 = *(const float2*)(wp1 + kt * 128 + lane * 2);
            float2 bl1 = *(const float2*)(wp1 + kt * 128 + 64 + lane * 2);
            mma8(eA0, eA1, eA2, eA3, ah[kt][0], ah[kt][1], ah[kt][2], ah[kt][3], bh0.x, bh0.y);
            mma8(fA0, fA1, fA2, fA3, ah[kt][0], ah[kt][1], ah[kt][2], ah[kt][3], bh1.x, bh1.y);
            mma8(eB0, eB1, eB2, eB3, al[kt][0], al[kt][1], al[kt][2], al[kt][3], bh0.x, bh0.y);
            mma8(fB0, fB1, fB2, fB3, al[kt][0], al[kt][1], al[kt][2], al[kt][3], bh1.x, bh1.y);
            mma8(eB0, eB1, eB2, eB3, ah[kt][0], ah[kt][1], ah[kt][2], ah[kt][3], bl0.x, bl0.y);
            mma8(fB0, fB1, fB2, fB3, ah[kt][0], ah[kt][1], ah[kt][2], ah[kt][3], bl1.x, bl1.y);
        }
        // thread-local full gate set: unit u = 4*pa + c4 (always < 25)
        float i0 = fast_sig(eA0 + eB0), f0 = fast_sig(eA1 + eB1);
        float g0 = fast_tanh(fA0 + fB0), o0 = fast_sig(fA1 + fB1);
        float i1 = fast_sig(eA2 + eB2), f1 = fast_sig(eA3 + eB3);
        float g1 = fast_tanh(fA2 + fB2), o1 = fast_sig(fA3 + fB3);
        float c0 = fmaf(f0, cst[pp * 2 + 0], i0 * g0);
        float c1 = fmaf(f1, cst[pp * 2 + 1], i1 * g1);
        cst[pp * 2 + 0] = c0; cst[pp * 2 + 1] = c1;
        float h0 = o0 * fast_tanh(c0);
        float h1 = o1 * fast_tanh(c1);
        const int u = 4 * pa + c4;
        const int cps = COLPOS(SELFC + u);
        vself[rA * ROWW + cps]       = h0;
        vself[(rA + 8) * ROWW + cps] = h1;
        if (vchild) {
            const int cpc = COLPOS(u);
            vchild[rA * 60 + cpc]       = h0;
            vchild[(rA + 8) * 60 + cpc] = h1;
        }
    }

    if (SPEC) {   // tile 12: unit 24, old 2-thread gate layout + shfl exchange
        float2 bb = *(const float2*)(biasL + 12 * 8 + 2 * c4);
        float eA0 = bb.x, eA1 = bb.y, eA2 = bb.x, eA3 = bb.y;
        float eB0 = 0.f, eB1 = 0.f, eB2 = 0.f, eB3 = 0.f;
        const float* wp = wb + 12 * KT * 128;
#pragma unroll
        for (int kt = 0; kt < KT; ++kt) {
            float2 bh = *(const float2*)(wp + kt * 128 + lane * 2);
            float2 bl = *(const float2*)(wp + kt * 128 + 64 + lane * 2);
            mma8(eA0, eA1, eA2, eA3, ah[kt][0], ah[kt][1], ah[kt][2], ah[kt][3], bh.x, bh.y);
            mma8(eB0, eB1, eB2, eB3, al[kt][0], al[kt][1], al[kt][2], al[kt][3], bh.x, bh.y);
            mma8(eB0, eB1, eB2, eB3, ah[kt][0], ah[kt][1], ah[kt][2], ah[kt][3], bl.x, bl.y);
        }
        const int podd = c4 & 1;
        const float kmul = podd ? 2.f : 1.f, kadd = podd ? -1.f : 0.f;
        float d0 = eA0 + eB0, d1 = eA1 + eB1, d2 = eA2 + eB2, d3 = eA3 + eB3;
        const int u = 24 + (c4 >> 1);
        float a0 = fmaf(kmul, fast_sig(kmul * d0), kadd);
        float a1 = fast_sig(d1);
        float a2 = fmaf(kmul, fast_sig(kmul * d2), kadd);
        float a3 = fast_sig(d3);
        float x0 = __shfl_xor_sync(0xFFFFFFFFu, a0, 1);
        float x1 = __shfl_xor_sync(0xFFFFFFFFu, a1, 1);
        float x2 = __shfl_xor_sync(0xFFFFFFFFu, a2, 1);
        float x3 = __shfl_xor_sync(0xFFFFFFFFu, a3, 1);
        float i0 = podd ? x0 : a0, f0 = podd ? x1 : a1;
        float g0 = podd ? a0 : x0, o0 = podd ? a1 : x1;
        float i1 = podd ? x2 : a2, f1 = podd ? x3 : a3;
        float g1 = podd ? a2 : x2, o1 = podd ? a3 : x3;
        float c0 = fmaf(f0, cst[NPAIR * 2 + 0], i0 * g0);
        float c1 = fmaf(f1, cst[NPAIR * 2 + 1], i1 * g1);
        float h0 = o0 * fast_tanh(c0);
        float h1 = o1 * fast_tanh(c1);
        if (u < 25) {
            cst[NPAIR * 2 + 0] = c0; cst[NPAIR * 2 + 1] = c1;
            if (!podd) {
                const int cps = COLPOS(SELFC + u);
                vself[rA * ROWW + cps]       = h0;
                vself[(rA + 8) * ROWW + cps] = h1;
            } else if (vchild) {
                const int cpc = COLPOS(u);
                vchild[rA * 60 + cpc]       = h0;
                vchild[(rA + 8) * 60 + cpc] = h1;
            }
        }
    }
}

__global__ void __launch_bounds__(NTHR) lstm_kernel(
    const float* __restrict__ x,
    const float* __restrict__ Wih1, const float* __restrict__ Whh1,
    const float* __restrict__ bih1, const float* __restrict__ bhh1,
    const float* __restrict__ Wih2, const float* __restrict__ Whh2,
    const float* __restrict__ bih2, const float* __restrict__ bhh2,
    const float* __restrict__ Wih3, const float* __restrict__ Whh3,
    const float* __restrict__ bih3, const float* __restrict__ bhh3,
    const float* __restrict__ Wih4, const float* __restrict__ Whh4,
    const float* __restrict__ bih4, const float* __restrict__ bhh4,
    const float* __restrict__ Wfc, const float* __restrict__ bfc,
    float* __restrict__ out, int write_states)
{
    extern __shared__ float smem[];
    const int tid = threadIdx.x, lane = tid & 31, wid = tid >> 5;
    const int gb0 = blockIdx.x * 32;
    const float* WihL[4] = {Wih1, Wih2, Wih3, Wih4};
    const float* WhhL[4] = {Whh1, Whh2, Whh3, Whh4};
    const float* bihL[4] = {bih1, bih2, bih3, bih4};
    const float* bhhL[4] = {bhh1, bhh2, bhh3, bhh4};

    // ---- stage B fragments (hi pass 0, lo pass 1), pair-relaid columns ----
    for (int i = tid; i < 6656; i += NTHR) {           // layer 1, KT=4
        int nt = i >> 9, r = i & 511, kt = r >> 7, r2 = r & 127;
        int pass = r2 >> 6, e = r2 & 63, ln = e >> 1, j = e & 1;
        int lc = ln >> 2;
        int k = kt * 8 + (ln & 3) + 4 * j;
        int u, gidx; col_map(nt, lc, u, gidx);
        float w = 0.f;
        if (u < 25) {
            int row = gidx * 25 + u;
            if (k == 0)       w = Wih1[row];
            else if (k <= 25) w = Whh1[row * 25 + k - 1];
        }
        float hi = tf_hi(w);
        smem[WB0_OFF + i] = pass ? (w - hi) : hi;
    }
    for (int i = tid; i < 34944; i += NTHR) {          // layers 2-4, KT=7
        int l = i / 11648, r0 = i - l * 11648;
        int nt = r0 / 896, r = r0 - nt * 896, kt = r >> 7, r2 = r & 127;
        int pass = r2 >> 6, e = r2 & 63, ln = e >> 1, j = e & 1;
        int lc = ln >> 2;
        int k = kt * 8 + (ln & 3) + 4 * j;
        int u, gidx; col_map(nt, lc, u, gidx);
        float w = 0.f;
        if (u < 25) {
            int row = gidx * 25 + u;
            if (k <= 24)                 w = WihL[l + 1][row * 25 + k];
            else if (k >= 28 && k <= 52) w = WhhL[l + 1][row * 25 + k - 28];
        }
        float hi = tf_hi(w);
        smem[WB123_OFF + i] = pass ? (w - hi) : hi;
    }
    for (int i = tid; i < 416; i += NTHR) {            // bias in new col order
        int l = i / 104, c = i - l * 104;
        int u, gidx; col_map(c >> 3, c & 7, u, gidx);
        smem[BIAS_OFF + i] = (u < 25) ? (bihL[l][gidx * 25 + u] + bhhL[l][gidx * 25 + u]) : 0.f;
    }
    for (int i = tid; i < 64; i += NTHR) {             // wfc in interleaved positions
        int grp = i >> 3, idx = i & 7;
        int k = grp * 8 + ((idx & 1) << 2) + (idx >> 1);
        smem[WFC_OFF + i] = (k >= 28 && k < 53) ? Wfc[k - 28] : 0.f;
    }
    for (int i = tid; i < 2304 + 11520; i += NTHR) smem[V0_OFF + i] = 0.f;

    const int layer = wid >> 2, mt = (wid & 3) >> 1, nth = wid & 1;
    const int rA = mt * 16 + (lane >> 2);

    float xreg = 0.f, bfc_reg = 0.f;
    if (wid == 16) {
        smem[V0_OFF + lane * 36] = x[gb0 + lane];      // logical col 0 -> pos 0
        xreg = x[(size_t)NB + gb0 + lane];
    }
    if (wid == 17) bfc_reg = bfc[0];
    __syncthreads();

    float cst[8];
#pragma unroll
    for (int i = 0; i < 8; ++i) cst[i] = 0.f;

    for (int T = 0; T < NTICKS; ++T) {
        if (wid == 16) {                               // x stager
            smem[V0_OFF + ((T + 1) & 1) * 1152 + lane * 36] = xreg;
            int t2 = (T + 2 < Tlen) ? T + 2 : Tlen - 1;
            xreg = x[(size_t)t2 * NB + gb0 + lane];
        }
        if (wid == 17 && T >= 4) {                     // fc: y(T-4)
            const ulonglong2* V3 = (const ulonglong2*)(smem + V123_OFF + 2 * 3840
                                   + ((T + 1) & 1) * 1920 + lane * 60);
            const ulonglong2* WF = (const ulonglong2*)(smem + WFC_OFF);
            ull A = pack2(bfc_reg, 0.f), B = 0ull;
#pragma unroll
            for (int ch = 6; ch < 14; ++ch) {          // positions 24..55 cover k 28..52
                ulonglong2 hv = V3[ch]; ulonglong2 w = WF[ch];
                fma2(A, w.x, hv.x); fma2(B, w.y, hv.y);
            }
            out[(size_t)(T - 4) * NB + gb0 + lane] = hsum2(A) + hsum2(B);
        }
        if (wid < 16 && T >= layer && T - layer < Tlen) {
            const int par = (T + layer) & 1;
            if (layer == 0) {
                const float* vr = smem + V0_OFF + par * 1152;
                float* vs = smem + V0_OFF + (par ^ 1) * 1152;
                float* vc = smem + V123_OFF + par * 1920;
                if (nth == 0)
                    layer_tick<4, 36, 1, 0, 3, 1>(vr, vs, vc, smem + WB0_OFF,
                                                  smem + BIAS_OFF, cst, lane, rA);
                else
                    layer_tick<4, 36, 1, 3, 3, 0>(vr, vs, vc, smem + WB0_OFF,
                                                  smem + BIAS_OFF, cst, lane, rA);
            } else {
                const float* vr = smem + V123_OFF + (layer - 1) * 3840 + par * 1920;
                float* vs = smem + V123_OFF + (layer - 1) * 3840 + (par ^ 1) * 1920;
                float* vc = (layer < 3) ? smem + V123_OFF + layer * 3840 + par * 1920
                                        : (float*)0;
                const float* wb = smem + WB123_OFF + (layer - 1) * 11648;
                const float* bs = smem + BIAS_OFF + layer * 104;
                if (nth == 0)
                    layer_tick<7, 60, 28, 0, 3, 1>(vr, vs, vc, wb, bs, cst, lane, rA);
                else
                    layer_tick<7, 60, 28, 3, 3, 0>(vr, vs, vc, wb, bs, cst, lane, rA);
            }
        }
        __syncthreads();
    }

    // ---- final states ----
    if (write_states && wid < 16) {
        size_t base = (size_t)Tlen * NB;
        const size_t S = (size_t)NB * 25;
        const int c4 = lane & 3;
        const int roww  = (layer == 0) ? 36 : 60;
        const int selfc = (layer == 0) ? 1 : 28;
        const float* vb0 = (layer == 0) ? smem + V0_OFF
                          : smem + V123_OFF + (layer - 1) * 3840;
        const int P0 = nth ? 3 : 0;
#pragma unroll
        for (int pi = 0; pi < 3; ++pi) {
            const int u = 4 * (P0 + pi) + c4;
            const int cps = COLPOS(selfc + u);
#pragma unroll
            for (int r2 = 0; r2 < 2; ++r2) {
                int row = rA + 8 * r2;
                size_t idx = (size_t)(gb0 + row) * 25 + u;
                out[base + (size_t)(2 * layer) * S + idx]     = vb0[row * roww + cps];
                out[base + (size_t)(2 * layer + 1) * S + idx] = cst[pi * 2 + r2];
            }
        }
        if (nth == 0 && c4 == 0) {                    // special tile: unit 24
            const int cps = COLPOS(selfc + 24);
#pragma unroll
            for (int r2 = 0; r2 < 2; ++r2) {
                int row = rA + 8 * r2;
                size_t idx = (size_t)(gb0 + row) * 25 + 24;
                out[base + (size_t)(2 * layer) * S + idx]     = vb0[row * roww + cps];
                out[base + (size_t)(2 * layer + 1) * S + idx] = cst[6 + r2];
            }
        }
    }
}

extern "C" void kernel_launch(void* const* d_in, const int* in_sizes, int n_in,
                              void* d_out, int out_size) {
    (void)n_in; (void)in_sizes;
    const float* a[19];
    for (int i = 0; i < 19; ++i) a[i] = (const float*)d_in[i];
    int smem_bytes = SMEM_FLOATS * (int)sizeof(float);
    static int configured = -1;
    if (configured != smem_bytes) {
        cudaFuncSetAttribute(lstm_kernel,
                             cudaFuncAttributeMaxDynamicSharedMemorySize, smem_bytes);
        configured = smem_bytes;
    }
    int write_states = (out_size >= Tlen * NB + 8 * NB * 25) ? 1 : 0;
    lstm_kernel<<<NB / 32, NTHR, smem_bytes>>>(
        a[0], a[1], a[2], a[3], a[4], a[5], a[6], a[7], a[8], a[9],
        a[10], a[11], a[12], a[13], a[14], a[15], a[16], a[17], a[18],
        (float*)d_out, write_states);
}